// round 3
// baseline (speedup 1.0000x reference)
#include <cuda_runtime.h>
#include <math.h>
#include <stdint.h>

// Problem constants
#define L_  6
#define B_  16
#define T_  2048
#define D_  768
#define V_  50280
#define R_  96               // L_*B_ rows
#define PW  1572             // ceil(V_/32) bitmap words per batch row
#define NTILE 128            // vocab tile per block
#define NT  393              // ceil(V_/NTILE)
#define KB  32               // K chunk

// -------- device scratch (no allocations allowed) --------
__device__ unsigned int g_present[B_ * PW];
__device__ float g_h[R_ * D_];
__device__ float g_pm[NT * R_];
__device__ float g_ps[NT * R_];
__device__ int   g_pi[NT * R_];
__device__ float g_rownll[R_];
__device__ float g_rowacc[R_];
__device__ int   g_rowvalid[R_];

// -------- packed f32x2 helpers --------
#define PACK2(d, lo, hi) \
    asm("mov.b64 %0, {%1, %2};" : "=l"(d) : "f"(lo), "f"(hi))
#define FMA2(acc, a, b) \
    asm("fma.rn.f32x2 %0, %1, %2, %0;" : "+l"(acc) : "l"(a), "l"(b))

__device__ __forceinline__ float2 unpack2(unsigned long long v) {
    float2 f;
    f.x = __uint_as_float((unsigned)(v & 0xffffffffull));
    f.y = __uint_as_float((unsigned)(v >> 32));
    return f;
}

// online-softmax + first-occurrence-argmax merge: (m,s,bi) <- combine with (m2,s2,bi2)
__device__ __forceinline__ void sm_combine(float& m, float& s, int& bi,
                                           float m2, float s2, int bi2) {
    if (m2 > m) {
        s = s * __expf(m - m2) + s2;   // m==-inf -> s==0, expf(-inf)=0 -> s=s2
        m = m2;
        bi = bi2;
    } else if (m2 == m) {
        s += s2;
        if (bi2 < bi) bi = bi2;        // first-occurrence tie-break (jnp.argmax)
    } else {
        s += s2 * __expf(m2 - m);      // m2==-inf -> s2==0 -> +0
    }
}

// -------- kernels --------
__global__ void zero_present_kernel() {
    int i = blockIdx.x * blockDim.x + threadIdx.x;
    if (i < B_ * PW) g_present[i] = 0u;
}

__global__ void scatter_kernel(const int* __restrict__ ids) {
    int i = blockIdx.x * blockDim.x + threadIdx.x;
    if (i < B_ * T_) {
        int b = i / T_;
        int tok = ids[i];
        if (tok >= 0 && tok < V_)
            atomicOr(&g_present[b * PW + (tok >> 5)], 1u << (tok & 31));
    }
}

__global__ void gather_kernel(const float* __restrict__ x,
                              const int* __restrict__ astarts) {
    int r = blockIdx.x;                 // r = l*B_ + b
    int b = r & (B_ - 1);
    int tt = astarts[b] - 1;
    if (tt < 0) tt = 0;
    if (tt >= T_) tt = T_ - 1;
    size_t base = ((size_t)r * T_ + (size_t)tt) * D_;
    for (int d = threadIdx.x; d < D_; d += blockDim.x)
        g_h[r * D_ + d] = x[base + d];
}

// GEMM: 96 x 128-vocab tile, K=768, fused mask + online softmax + argmax epilogue.
// Block: 192 threads = 16 vocab-threads (x8 v each) * 12 row-threads (x8 rows each).
__global__ void __launch_bounds__(192, 2) gemm_kernel(const float* __restrict__ w) {
    __shared__ float wsm[KB * NTILE];   // [kk][v_local]
    __shared__ float hsm[KB * R_];      // [kk][row]

    const int tile  = blockIdx.x;
    const int vbase = tile * NTILE;
    const int t  = threadIdx.x;
    const int vt = t & 15;              // vocab-thread 0..15
    const int rt = t >> 4;              // row-thread   0..11

    unsigned long long acc[8][4];       // 8 rows x 4 f32x2 vocab pairs
#pragma unroll
    for (int i = 0; i < 8; i++)
#pragma unroll
        for (int j = 0; j < 4; j++) acc[i][j] = 0ull;

    for (int k0 = 0; k0 < D_; k0 += KB) {
        __syncthreads();
        // W tile: 128 vocab x 32 k, transposed to kk-major. float4 gmem loads.
        for (int idx = t; idx < NTILE * (KB / 4); idx += 192) {
            int vl = idx & (NTILE - 1);
            int q  = idx >> 7;          // 0..7
            int v  = vbase + vl;
            float4 val = make_float4(0.f, 0.f, 0.f, 0.f);
            if (v < V_)
                val = *reinterpret_cast<const float4*>(w + (size_t)v * D_ + k0 + q * 4);
            wsm[(q * 4 + 0) * NTILE + vl] = val.x;
            wsm[(q * 4 + 1) * NTILE + vl] = val.y;
            wsm[(q * 4 + 2) * NTILE + vl] = val.z;
            wsm[(q * 4 + 3) * NTILE + vl] = val.w;
        }
        // H tile: 96 rows x 32 k, kk-major.
        for (int idx = t; idx < R_ * (KB / 4); idx += 192) {
            int r = idx % R_;
            int q = idx / R_;
            float4 val = *reinterpret_cast<const float4*>(g_h + r * D_ + k0 + q * 4);
            hsm[(q * 4 + 0) * R_ + r] = val.x;
            hsm[(q * 4 + 1) * R_ + r] = val.y;
            hsm[(q * 4 + 2) * R_ + r] = val.z;
            hsm[(q * 4 + 3) * R_ + r] = val.w;
        }
        __syncthreads();

#pragma unroll 8
        for (int kk = 0; kk < KB; kk++) {
            const float4* hp = reinterpret_cast<const float4*>(hsm + kk * R_ + rt * 8);
            float4 ha = hp[0];
            float4 hb = hp[1];
            const float4* wp = reinterpret_cast<const float4*>(wsm + kk * NTILE + vt * 8);
            float4 wa = wp[0];
            float4 wb = wp[1];

            unsigned long long h2[8], w2[4];
            PACK2(h2[0], ha.x, ha.x); PACK2(h2[1], ha.y, ha.y);
            PACK2(h2[2], ha.z, ha.z); PACK2(h2[3], ha.w, ha.w);
            PACK2(h2[4], hb.x, hb.x); PACK2(h2[5], hb.y, hb.y);
            PACK2(h2[6], hb.z, hb.z); PACK2(h2[7], hb.w, hb.w);
            PACK2(w2[0], wa.x, wa.y); PACK2(w2[1], wa.z, wa.w);
            PACK2(w2[2], wb.x, wb.y); PACK2(w2[3], wb.z, wb.w);

#pragma unroll
            for (int i = 0; i < 8; i++)
#pragma unroll
                for (int j = 0; j < 4; j++)
                    FMA2(acc[i][j], h2[i], w2[j]);
        }
    }

    // ---- fused epilogue: mask, online softmax, argmax (per row, this tile) ----
    float m[8], s[8];
    int bi[8];
#pragma unroll
    for (int i = 0; i < 8; i++) { m[i] = -INFINITY; s[i] = 0.f; bi[i] = 0x7fffffff; }

#pragma unroll
    for (int i = 0; i < 8; i++) {
        int row = rt * 8 + i;
        int b = row & (B_ - 1);
        const unsigned int* pres = g_present + b * PW;
#pragma unroll
        for (int j = 0; j < 8; j++) {
            int v = vbase + vt * 8 + j;
            if (v < V_) {
                unsigned int wd = pres[v >> 5];
                if ((wd >> (v & 31)) & 1u) {
                    float2 p = unpack2(acc[i][j >> 1]);
                    float x = (j & 1) ? p.y : p.x;
                    sm_combine(m[i], s[i], bi[i], x, 1.0f, v);
                }
            }
        }
    }
    // reduce across the 16 vocab-threads (one 16-lane shuffle segment per row group)
#pragma unroll
    for (int off = 8; off; off >>= 1) {
#pragma unroll
        for (int i = 0; i < 8; i++) {
            float m2 = __shfl_down_sync(0xffffffffu, m[i], off, 16);
            float s2 = __shfl_down_sync(0xffffffffu, s[i], off, 16);
            int   b2 = __shfl_down_sync(0xffffffffu, bi[i], off, 16);
            sm_combine(m[i], s[i], bi[i], m2, s2, b2);
        }
    }
    if (vt == 0) {
#pragma unroll
        for (int i = 0; i < 8; i++) {
            int row = rt * 8 + i;
            g_pm[tile * R_ + row] = m[i];
            g_ps[tile * R_ + row] = s[i];
            g_pi[tile * R_ + row] = bi[i];
        }
    }
}

// Per-row reduction over the 393 tile partials + tgt logit dot product.
__global__ void reduce_rows_kernel(const float* __restrict__ w,
                                   const int* __restrict__ tgts,
                                   const int* __restrict__ astarts) {
    __shared__ float smm[128], sms[128], sdot[128];
    __shared__ int smi[128];
    const int r = blockIdx.x;           // r = l*16 + b
    const int t = threadIdx.x;
    const int b = r & (B_ - 1);
    const int l = r >> 4;

    float m = -INFINITY, s = 0.f;
    int bi = 0x7fffffff;
    for (int tile = t; tile < NT; tile += 128)
        sm_combine(m, s, bi, g_pm[tile * R_ + r], g_ps[tile * R_ + r], g_pi[tile * R_ + r]);
    smm[t] = m; sms[t] = s; smi[t] = bi;

    // logit at target: dot(h[r], w[tgt])
    int tgt = tgts[b * L_ + l];         // chain_targets is (B, L)
    int tc = (tgt >= 0 && tgt < V_) ? tgt : 0;
    float dot = 0.f;
    for (int d = t; d < D_; d += 128)
        dot += w[(size_t)tc * D_ + d] * g_h[r * D_ + d];
    sdot[t] = dot;
    __syncthreads();

    for (int off = 64; off; off >>= 1) {
        if (t < off) {
            sm_combine(smm[t], sms[t], smi[t], smm[t + off], sms[t + off], smi[t + off]);
            sdot[t] += sdot[t + off];
        }
        __syncthreads();
    }

    if (t == 0) {
        float lse = smm[0] + logf(sms[0]);
        float nll = lse - sdot[0];
        int as = astarts[b];
        bool in_range = (as >= 1) && (as < T_);
        bool ptgt = (tgt >= 0 && tgt < V_) &&
                    ((g_present[b * PW + (tgt >> 5)] >> (tgt & 31)) & 1u);
        bool valid = ptgt && in_range;
        int pred = smi[0];
        g_rownll[r]   = valid ? nll : 0.f;
        g_rowacc[r]   = (valid && pred == tgt) ? 1.f : 0.f;
        g_rowvalid[r] = valid ? 1 : 0;
    }
}

__global__ void finalize_kernel(float* __restrict__ out) {
    if (threadIdx.x == 0) {
        float avg_loss = 0.f, avg_acc = 0.f, final_acc = 0.f;
        int nhas = 0;
        for (int l = 0; l < L_; l++) {
            float cnt = 0.f, sl = 0.f, sa = 0.f;
            for (int b = 0; b < B_; b++) {
                int r = l * B_ + b;
                cnt += (float)g_rowvalid[r];
                sl  += g_rownll[r];
                sa  += g_rowacc[r];
            }
            float denom = fmaxf(cnt, 1.f);
            float ll = sl / denom;
            float la = sa / denom;
            if (cnt > 0.f) { nhas++; avg_loss += ll; avg_acc += la; }
            if (l == L_ - 1) final_acc = la;
        }
        float nv = fmaxf((float)nhas, 1.f);
        out[0] = avg_loss / nv;
        out[1] = avg_acc / nv;
        out[2] = final_acc;
    }
}

extern "C" void kernel_launch(void* const* d_in, const int* in_sizes, int n_in,
                              void* d_out, int out_size) {
    // Identify inputs by element count (all distinct) — robust to ordering.
    const float* x = nullptr;
    const float* w = nullptr;
    const int* ids = nullptr;
    const int* tgts = nullptr;
    const int* astarts = nullptr;
    for (int i = 0; i < n_in; i++) {
        long sz = (long)in_sizes[i];
        if (sz == (long)L_ * B_ * T_ * D_)      x = (const float*)d_in[i];
        else if (sz == (long)V_ * D_)           w = (const float*)d_in[i];
        else if (sz == (long)B_ * T_)           ids = (const int*)d_in[i];
        else if (sz == (long)B_ * L_)           tgts = (const int*)d_in[i];
        else if (sz == (long)B_)                astarts = (const int*)d_in[i];
    }

    zero_present_kernel<<<(B_ * PW + 255) / 256, 256>>>();
    scatter_kernel<<<(B_ * T_ + 255) / 256, 256>>>(ids);
    gather_kernel<<<R_, 256>>>(x, astarts);
    gemm_kernel<<<NT, 192>>>(w);
    reduce_rows_kernel<<<R_, 128>>>(w, tgts, astarts);
    finalize_kernel<<<1, 32>>>((float*)d_out);
}